// round 5
// baseline (speedup 1.0000x reference)
#include <cuda_runtime.h>
#include <cuda_bf16.h>
#include <cstdint>

#define PLANES 80
#define FLAT   5120      // 80 * 64
#define NMOVES 1858
#define BATCH  16384
#define ROW_BYTES (FLAT * 4)      // 20480
#define GRID   740                // ~5 CTAs/SM on 148 SMs @ 41KB smem

// scan tiling: each tile = 256 threads x 8 uint4 = 2048 uint4 = 32KB
#define TOTAL4  (FLAT * NMOVES / 4)            // 2,378,240 uint4
#define TILE_U4 2048
#define NTILES  ((TOTAL4 + TILE_U4 - 1) / TILE_U4)   // 1162

// move -> flat-index map, rebuilt every launch
__device__ __align__(16) int g_idx[NMOVES];
// [0] = tile claim counter, [1] = tiles-done counter (memset to 0 per launch)
__device__ unsigned int g_ctrs[2];

// ---------------------------------------------------------------------------
// PTX helpers
// ---------------------------------------------------------------------------
__device__ __forceinline__ uint32_t smem_u32(const void* p) {
    uint32_t a;
    asm("{ .reg .u64 t; cvta.to.shared.u64 t, %1; cvt.u32.u64 %0, t; }"
        : "=r"(a) : "l"(p));
    return a;
}
__device__ __forceinline__ void mbar_init(uint32_t addr, uint32_t count) {
    asm volatile("mbarrier.init.shared.b64 [%0], %1;" :: "r"(addr), "r"(count) : "memory");
}
__device__ __forceinline__ void mbar_expect_tx(uint32_t addr, uint32_t bytes) {
    asm volatile("mbarrier.arrive.expect_tx.shared.b64 _, [%0], %1;"
                 :: "r"(addr), "r"(bytes) : "memory");
}
__device__ __forceinline__ void bulk_g2s(uint32_t dst_smem, const void* gsrc,
                                         uint32_t bytes, uint32_t mbar) {
    asm volatile(
        "cp.async.bulk.shared::cta.global.mbarrier::complete_tx::bytes "
        "[%0], [%1], %2, [%3];"
        :: "r"(dst_smem), "l"(gsrc), "r"(bytes), "r"(mbar) : "memory");
}
__device__ __forceinline__ void mbar_wait(uint32_t addr, uint32_t phase) {
    asm volatile(
        "{\n\t"
        ".reg .pred P;\n\t"
        "W%=:\n\t"
        "mbarrier.try_wait.parity.acquire.cta.shared::cta.b64 P, [%0], %1, 0x989680;\n\t"
        "@!P bra W%=;\n\t"
        "}"
        :: "r"(addr), "r"(phase) : "memory");
}

// ---------------------------------------------------------------------------
// Fused kernel: scan fc1 (dynamic tiles) -> device-wide ready flag ->
// persistent double-buffered TMA gather.
// ---------------------------------------------------------------------------
__global__ __launch_bounds__(256)
void fused_policy_kernel(const float* __restrict__ x,
                         const uint4* __restrict__ fc1v,
                         float* __restrict__ out,
                         int nrows) {
    __shared__ __align__(128) float rowbuf[2][FLAT];     // 40 KB
    __shared__ __align__(8) unsigned long long mbar[2];
    __shared__ unsigned int s_tile;

    const int tid = threadIdx.x;
    const int bid = blockIdx.x;
    const uint32_t mb[2] = { smem_u32(&mbar[0]), smem_u32(&mbar[1]) };
    const uint32_t rb[2] = { smem_u32(rowbuf[0]), smem_u32(rowbuf[1]) };

    if (tid == 0) { mbar_init(mb[0], 1); mbar_init(mb[1], 1); }
    __syncthreads();

    // ---- prefetch first two x rows NOW (independent of g_idx) ----
    if (tid == 0) {
        mbar_expect_tx(mb[0], ROW_BYTES);
        bulk_g2s(rb[0], x + (size_t)bid * FLAT, ROW_BYTES, mb[0]);
        mbar_expect_tx(mb[1], ROW_BYTES);
        bulk_g2s(rb[1], x + (size_t)(bid + GRID) * FLAT, ROW_BYTES, mb[1]);
    }

    // ---- phase 1: scan fc1 via dynamically claimed tiles ----
    unsigned int my_tiles = 0;
    for (;;) {
        if (tid == 0) s_tile = atomicAdd(&g_ctrs[0], 1u);
        __syncthreads();
        const unsigned int tile = s_tile;
        __syncthreads();               // s_tile consumed before next overwrite
        if (tile >= NTILES) break;
        my_tiles++;

        const int base = (int)tile * TILE_U4 + tid;
        #pragma unroll
        for (int j = 0; j < 8; j++) {
            const int t = base + j * 256;
            if (t < TOTAL4) {
                uint4 v = fc1v[t];
                if (v.x | v.y | v.z | v.w) {   // <=1858 hits in 9.5M elems
                    long long e = (long long)t * 4;
                    if (v.x) { long long ek = e + 0; g_idx[(int)(ek % NMOVES)] = (int)(ek / NMOVES); }
                    if (v.y) { long long ek = e + 1; g_idx[(int)(ek % NMOVES)] = (int)(ek / NMOVES); }
                    if (v.z) { long long ek = e + 2; g_idx[(int)(ek % NMOVES)] = (int)(ek / NMOVES); }
                    if (v.w) { long long ek = e + 3; g_idx[(int)(ek % NMOVES)] = (int)(ek / NMOVES); }
                }
            }
        }
    }

    // publish processed-tile count (order g_idx writes before the count)
    __syncthreads();
    if (tid == 0 && my_tiles) {
        __threadfence();
        atomicAdd(&g_ctrs[1], my_tiles);
    }

    // ---- device-wide wait: all tiles processed ----
    if (tid == 0) {
        while (atomicAdd(&g_ctrs[1], 0u) != NTILES) __nanosleep(64);
        __threadfence();   // acquire side
    }
    __syncthreads();

    // ---- preload gather indices into registers (reused every row) ----
    const int2* idxp = reinterpret_cast<const int2*>(g_idx);
    const int2 i0 = idxp[tid];
    const int2 i1 = idxp[tid + 256];
    const int2 i2 = idxp[tid + 512];
    const bool has3 = tid < (NMOVES / 2 - 768);           // 161 threads
    const int2 i3 = has3 ? idxp[tid + 768] : make_int2(0, 0);

    // ---- phase 2: double-buffered gather ----
    int buf = 0;
    int phase[2] = {0, 0};
    for (int r = bid; r < nrows; r += GRID) {
        mbar_wait(mb[buf], phase[buf]);
        phase[buf] ^= 1;

        const float* rw = rowbuf[buf];
        float2* o = reinterpret_cast<float2*>(out + (size_t)r * NMOVES);
        float2 v;
        v.x = rw[i0.x]; v.y = rw[i0.y]; __stcs(o + tid,       v);
        v.x = rw[i1.x]; v.y = rw[i1.y]; __stcs(o + tid + 256, v);
        v.x = rw[i2.x]; v.y = rw[i2.y]; __stcs(o + tid + 512, v);
        if (has3) {
            v.x = rw[i3.x]; v.y = rw[i3.y]; __stcs(o + tid + 768, v);
        }
        __syncthreads();   // buffer fully consumed before refill

        const int rn = r + 2 * GRID;   // refill this buffer 2 steps ahead
        if (tid == 0 && rn < nrows) {
            mbar_expect_tx(mb[buf], ROW_BYTES);
            bulk_g2s(rb[buf], x + (size_t)rn * FLAT, ROW_BYTES, mb[buf]);
        }
        buf ^= 1;
    }
}

extern "C" void kernel_launch(void* const* d_in, const int* in_sizes, int n_in,
                              void* d_out, int out_size) {
    const float* x   = (const float*)d_in[0];   // [16384, 80, 8, 8] fp32
    const float* fc1 = (const float*)d_in[1];   // [5120, 1858] fp32
    float* out = (float*)d_out;                 // [16384, 1858] fp32

    // reset work-queue + done counters (graph memset node; no allocation)
    void* ctrs = nullptr;
    cudaGetSymbolAddress(&ctrs, g_ctrs);
    cudaMemsetAsync(ctrs, 0, 2 * sizeof(unsigned int));

    fused_policy_kernel<<<GRID, 256>>>(
        x, reinterpret_cast<const uint4*>(fc1), out, BATCH);
}

// round 6
// speedup vs baseline: 1.0498x; 1.0498x over previous
#include <cuda_runtime.h>
#include <cuda_bf16.h>
#include <cstdint>

#define PLANES 80
#define FLAT   5120      // 80 * 64
#define NMOVES 1858
#define BATCH  16384
#define ROW_BYTES (FLAT * 4)              // 20480

// fc1 scan tiling: 581 blocks x (256 threads x 16 uint4) = 64KB tiles
#define TOTAL4  (FLAT * NMOVES / 4)       // 2,378,240 uint4
#define TILE_U4 4096
#define NSCAN   ((TOTAL4 + TILE_U4 - 1) / TILE_U4)   // 581

// move -> flat-index map, rebuilt every launch
__device__ __align__(16) int g_idx[NMOVES];
// tiles-done counter (memset to 0 per launch via graph memset node)
__device__ unsigned int g_done;

// ---------------------------------------------------------------------------
// PTX helpers
// ---------------------------------------------------------------------------
__device__ __forceinline__ uint32_t smem_u32(const void* p) {
    uint32_t a;
    asm("{ .reg .u64 t; cvta.to.shared.u64 t, %1; cvt.u32.u64 %0, t; }"
        : "=r"(a) : "l"(p));
    return a;
}
__device__ __forceinline__ void mbar_init(uint32_t addr, uint32_t count) {
    asm volatile("mbarrier.init.shared.b64 [%0], %1;" :: "r"(addr), "r"(count) : "memory");
}
__device__ __forceinline__ void mbar_expect_tx(uint32_t addr, uint32_t bytes) {
    asm volatile("mbarrier.arrive.expect_tx.shared.b64 _, [%0], %1;"
                 :: "r"(addr), "r"(bytes) : "memory");
}
__device__ __forceinline__ void bulk_g2s(uint32_t dst_smem, const void* gsrc,
                                         uint32_t bytes, uint32_t mbar) {
    asm volatile(
        "cp.async.bulk.shared::cta.global.mbarrier::complete_tx::bytes "
        "[%0], [%1], %2, [%3];"
        :: "r"(dst_smem), "l"(gsrc), "r"(bytes), "r"(mbar) : "memory");
}
__device__ __forceinline__ void mbar_wait(uint32_t addr, uint32_t phase) {
    asm volatile(
        "{\n\t"
        ".reg .pred P;\n\t"
        "W%=:\n\t"
        "mbarrier.try_wait.parity.acquire.cta.shared::cta.b64 P, [%0], %1, 0x989680;\n\t"
        "@!P bra W%=;\n\t"
        "}"
        :: "r"(addr), "r"(phase) : "memory");
}
__device__ __forceinline__ unsigned int ld_acquire(const unsigned int* p) {
    unsigned int v;
    asm volatile("ld.acquire.gpu.u32 %0, [%1];" : "=r"(v) : "l"(p) : "memory");
    return v;
}

// ---------------------------------------------------------------------------
// Fused kernel, R3-shaped: one CTA per batch row (grid = 16384, 8 CTAs/SM).
// Every block: issue TMA stage of its row -> (first 581 blocks: scan one fc1
// tile, publish) -> wait done==581 -> preload indices -> gather -> store.
// ---------------------------------------------------------------------------
__global__ __launch_bounds__(256, 8)
void fused_policy_kernel(const float* __restrict__ x,
                         const uint4* __restrict__ fc1v,
                         float* __restrict__ out) {
    __shared__ __align__(128) float row[FLAT];           // 20 KB
    __shared__ __align__(8) unsigned long long mbar;

    const int tid = threadIdx.x;
    const int bid = blockIdx.x;
    const uint32_t mbar_a = smem_u32(&mbar);
    const uint32_t row_a  = smem_u32(row);

    if (tid == 0) mbar_init(mbar_a, 1);
    __syncthreads();
    if (tid == 0) {
        mbar_expect_tx(mbar_a, ROW_BYTES);
        bulk_g2s(row_a, x + (size_t)bid * FLAT, ROW_BYTES, mbar_a);
    }

    // ---- scan phase: only the first NSCAN blocks participate ----
    if (bid < NSCAN) {
        const int base = bid * TILE_U4 + tid;
        #pragma unroll 4
        for (int j = 0; j < 16; j++) {
            const int t = base + j * 256;
            if (t < TOTAL4) {
                uint4 v = fc1v[t];
                if (v.x | v.y | v.z | v.w) {   // <=1858 hits in 9.5M elems
                    long long e = (long long)t * 4;
                    if (v.x) { long long ek = e;     g_idx[(int)(ek % NMOVES)] = (int)(ek / NMOVES); }
                    if (v.y) { long long ek = e + 1; g_idx[(int)(ek % NMOVES)] = (int)(ek / NMOVES); }
                    if (v.z) { long long ek = e + 2; g_idx[(int)(ek % NMOVES)] = (int)(ek / NMOVES); }
                    if (v.w) { long long ek = e + 3; g_idx[(int)(ek % NMOVES)] = (int)(ek / NMOVES); }
                }
            }
        }
        __syncthreads();
        if (tid == 0) {
            __threadfence();                       // release g_idx writes
            atomicAdd(&g_done, 1u);
        }
    }

    // ---- device-wide wait: all scan tiles published ----
    if (tid == 0) {
        while (ld_acquire(&g_done) != NSCAN) __nanosleep(32);
    }
    __syncthreads();

    // ---- gather ----
    const int2* idxp = reinterpret_cast<const int2*>(g_idx);
    const int2 i0 = idxp[tid];
    const int2 i1 = idxp[tid + 256];
    const int2 i2 = idxp[tid + 512];
    const bool has3 = tid < (NMOVES / 2 - 768);           // 161 threads
    const int2 i3 = has3 ? idxp[tid + 768] : make_int2(0, 0);

    mbar_wait(mbar_a, 0);

    float2* o = reinterpret_cast<float2*>(out + (size_t)bid * NMOVES);
    float2 v;
    v.x = row[i0.x]; v.y = row[i0.y]; __stcs(o + tid,       v);
    v.x = row[i1.x]; v.y = row[i1.y]; __stcs(o + tid + 256, v);
    v.x = row[i2.x]; v.y = row[i2.y]; __stcs(o + tid + 512, v);
    if (has3) {
        v.x = row[i3.x]; v.y = row[i3.y]; __stcs(o + tid + 768, v);
    }
}

extern "C" void kernel_launch(void* const* d_in, const int* in_sizes, int n_in,
                              void* d_out, int out_size) {
    const float* x   = (const float*)d_in[0];   // [16384, 80, 8, 8] fp32
    const float* fc1 = (const float*)d_in[1];   // [5120, 1858] fp32
    float* out = (float*)d_out;                 // [16384, 1858] fp32

    // reset the done counter (graph memset node; no allocation)
    void* ctr = nullptr;
    cudaGetSymbolAddress(&ctr, g_done);
    cudaMemsetAsync(ctr, 0, sizeof(unsigned int));

    fused_policy_kernel<<<BATCH, 256>>>(
        x, reinterpret_cast<const uint4*>(fc1), out);
}

// round 7
// speedup vs baseline: 1.1560x; 1.1012x over previous
#include <cuda_runtime.h>
#include <cuda_bf16.h>
#include <cstdint>

#define PLANES 80
#define FLAT   5120      // 80 * 64
#define NMOVES 1858
#define BATCH  16384
#define ROW_BYTES (FLAT * 4)   // 20480

// move -> flat-index map, rebuilt every launch (deterministic per call).
__device__ __align__(16) int g_idx[NMOVES];

// ---------------------------------------------------------------------------
// PTX helpers
// ---------------------------------------------------------------------------
__device__ __forceinline__ uint32_t smem_u32(const void* p) {
    uint32_t a;
    asm("{ .reg .u64 t; cvta.to.shared.u64 t, %1; cvt.u32.u64 %0, t; }"
        : "=r"(a) : "l"(p));
    return a;
}
__device__ __forceinline__ void mbar_init(uint32_t addr, uint32_t count) {
    asm volatile("mbarrier.init.shared.b64 [%0], %1;" :: "r"(addr), "r"(count) : "memory");
}
__device__ __forceinline__ void mbar_expect_tx(uint32_t addr, uint32_t bytes) {
    asm volatile("mbarrier.arrive.expect_tx.shared.b64 _, [%0], %1;"
                 :: "r"(addr), "r"(bytes) : "memory");
}
__device__ __forceinline__ void bulk_g2s(uint32_t dst_smem, const void* gsrc,
                                         uint32_t bytes, uint32_t mbar) {
    asm volatile(
        "cp.async.bulk.shared::cta.global.mbarrier::complete_tx::bytes "
        "[%0], [%1], %2, [%3];"
        :: "r"(dst_smem), "l"(gsrc), "r"(bytes), "r"(mbar) : "memory");
}
__device__ __forceinline__ void mbar_wait(uint32_t addr, uint32_t phase) {
    asm volatile(
        "{\n\t"
        ".reg .pred P;\n\t"
        "W%=:\n\t"
        "mbarrier.try_wait.parity.acquire.cta.shared::cta.b64 P, [%0], %1, 0x989680;\n\t"
        "@!P bra W%=;\n\t"
        "}"
        :: "r"(addr), "r"(phase) : "memory");
}

// ---------------------------------------------------------------------------
// Kernel A: recover src index per move column from the 0/1 selection matrix.
// Perfect tiling: 1858 blocks x 256 threads x 5 uint4 = 2,378,240 uint4
// exactly (= FLAT*NMOVES/4). No bounds checks, lane-contiguous 512B warp
// accesses, 5 independent loads in flight per thread.
// ---------------------------------------------------------------------------
__global__ __launch_bounds__(256)
void build_idx_kernel(const uint4* __restrict__ fc1v) {
    const int base = blockIdx.x * 1280 + threadIdx.x;   // 1280 = 256*5 uint4

    uint4 v0 = fc1v[base];
    uint4 v1 = fc1v[base + 256];
    uint4 v2 = fc1v[base + 512];
    uint4 v3 = fc1v[base + 768];
    uint4 v4 = fc1v[base + 1024];

    #pragma unroll
    for (int j = 0; j < 5; j++) {
        uint4 v = (j == 0) ? v0 : (j == 1) ? v1 : (j == 2) ? v2 : (j == 3) ? v3 : v4;
        if (v.x | v.y | v.z | v.w) {   // rare: <=1858 hits in 9.5M elems
            long long e = ((long long)base + j * 256) * 4;
            if (v.x) { long long ek = e;     g_idx[(int)(ek % NMOVES)] = (int)(ek / NMOVES); }
            if (v.y) { long long ek = e + 1; g_idx[(int)(ek % NMOVES)] = (int)(ek / NMOVES); }
            if (v.z) { long long ek = e + 2; g_idx[(int)(ek % NMOVES)] = (int)(ek / NMOVES); }
            if (v.w) { long long ek = e + 3; g_idx[(int)(ek % NMOVES)] = (int)(ek / NMOVES); }
        }
    }
}

// ---------------------------------------------------------------------------
// Kernel B (proven R3 shape, 62.4us @ 86.6% DRAM): out[b, m] = x[b, g_idx[m]].
// One CTA per batch row. TMA-stage the 20KB row, preload gather indices into
// registers while the copy is in flight, gather from smem, float2 .cs stores.
// ---------------------------------------------------------------------------
__global__ __launch_bounds__(256)
void policy_gather_kernel(const float* __restrict__ x,
                          float* __restrict__ out) {
    __shared__ __align__(128) float row[FLAT];           // 20 KB
    __shared__ __align__(8) unsigned long long mbar;

    const int tid = threadIdx.x;
    const int b = blockIdx.x;
    const uint32_t mbar_a = smem_u32(&mbar);
    const uint32_t row_a  = smem_u32(row);

    if (tid == 0) mbar_init(mbar_a, 1);
    __syncthreads();
    if (tid == 0) {
        mbar_expect_tx(mbar_a, ROW_BYTES);
        bulk_g2s(row_a, x + (size_t)b * FLAT, ROW_BYTES, mbar_a);
    }

    // Preload gather indices while the bulk copy is in flight.
    const int2* idxp = reinterpret_cast<const int2*>(g_idx);
    const int2 i0 = idxp[tid];
    const int2 i1 = idxp[tid + 256];
    const int2 i2 = idxp[tid + 512];
    const bool has3 = tid < (NMOVES / 2 - 768);          // 161 threads
    int2 i3 = make_int2(0, 0);
    if (has3) i3 = idxp[tid + 768];

    mbar_wait(mbar_a, 0);

    float2* o = reinterpret_cast<float2*>(out + (size_t)b * NMOVES);
    float2 v;
    v.x = row[i0.x]; v.y = row[i0.y]; __stcs(o + tid,       v);
    v.x = row[i1.x]; v.y = row[i1.y]; __stcs(o + tid + 256, v);
    v.x = row[i2.x]; v.y = row[i2.y]; __stcs(o + tid + 512, v);
    if (has3) {
        v.x = row[i3.x]; v.y = row[i3.y]; __stcs(o + tid + 768, v);
    }
}

extern "C" void kernel_launch(void* const* d_in, const int* in_sizes, int n_in,
                              void* d_out, int out_size) {
    const float* x   = (const float*)d_in[0];   // [16384, 80, 8, 8] fp32
    const float* fc1 = (const float*)d_in[1];   // [5120, 1858] fp32
    float* out = (float*)d_out;                 // [16384, 1858] fp32

    // A: rebuild the selection index (38 MB scan, perfectly tiled).
    build_idx_kernel<<<1858, 256>>>(reinterpret_cast<const uint4*>(fc1));

    // B: the gather (HBM-roofline bound).
    policy_gather_kernel<<<BATCH, 256>>>(x, out);
}

// round 8
// speedup vs baseline: 1.1693x; 1.0115x over previous
#include <cuda_runtime.h>
#include <cuda_bf16.h>
#include <cstdint>

#define PLANES 80
#define FLAT   5120      // 80 * 64
#define NMOVES 1858
#define BATCH  16384
#define ROW_BYTES (FLAT * 4)   // 20480

// move -> flat-index map, rebuilt every launch (deterministic per call).
__device__ __align__(16) int g_idx[NMOVES];

// ---------------------------------------------------------------------------
// PTX helpers
// ---------------------------------------------------------------------------
__device__ __forceinline__ uint32_t smem_u32(const void* p) {
    uint32_t a;
    asm("{ .reg .u64 t; cvta.to.shared.u64 t, %1; cvt.u32.u64 %0, t; }"
        : "=r"(a) : "l"(p));
    return a;
}
__device__ __forceinline__ void mbar_init(uint32_t addr, uint32_t count) {
    asm volatile("mbarrier.init.shared.b64 [%0], %1;" :: "r"(addr), "r"(count) : "memory");
}
__device__ __forceinline__ void mbar_expect_tx(uint32_t addr, uint32_t bytes) {
    asm volatile("mbarrier.arrive.expect_tx.shared.b64 _, [%0], %1;"
                 :: "r"(addr), "r"(bytes) : "memory");
}
__device__ __forceinline__ void bulk_g2s(uint32_t dst_smem, const void* gsrc,
                                         uint32_t bytes, uint32_t mbar) {
    asm volatile(
        "cp.async.bulk.shared::cta.global.mbarrier::complete_tx::bytes "
        "[%0], [%1], %2, [%3];"
        :: "r"(dst_smem), "l"(gsrc), "r"(bytes), "r"(mbar) : "memory");
}
__device__ __forceinline__ void mbar_wait(uint32_t addr, uint32_t phase) {
    asm volatile(
        "{\n\t"
        ".reg .pred P;\n\t"
        "W%=:\n\t"
        "mbarrier.try_wait.parity.acquire.cta.shared::cta.b64 P, [%0], %1, 0x989680;\n\t"
        "@!P bra W%=;\n\t"
        "}"
        :: "r"(addr), "r"(phase) : "memory");
}
// PDL controls
__device__ __forceinline__ void pdl_launch_dependents() {
    asm volatile("griddepcontrol.launch_dependents;" ::: "memory");
}
__device__ __forceinline__ void pdl_wait() {
    asm volatile("griddepcontrol.wait;" ::: "memory");
}

// ---------------------------------------------------------------------------
// Kernel A: recover src index per move column from the 0/1 selection matrix.
// Perfect tiling: 1858 blocks x 256 threads x 5 uint4 = 2,378,240 uint4.
// Fires launch_dependents at entry so the gather grid starts (and begins its
// x-row TMA staging) while this scan is still running.
// ---------------------------------------------------------------------------
__global__ __launch_bounds__(256)
void build_idx_kernel(const uint4* __restrict__ fc1v) {
    pdl_launch_dependents();

    const int base = blockIdx.x * 1280 + threadIdx.x;   // 1280 = 256*5 uint4

    uint4 v0 = fc1v[base];
    uint4 v1 = fc1v[base + 256];
    uint4 v2 = fc1v[base + 512];
    uint4 v3 = fc1v[base + 768];
    uint4 v4 = fc1v[base + 1024];

    #pragma unroll
    for (int j = 0; j < 5; j++) {
        uint4 v = (j == 0) ? v0 : (j == 1) ? v1 : (j == 2) ? v2 : (j == 3) ? v3 : v4;
        if (v.x | v.y | v.z | v.w) {   // rare: <=1858 hits in 9.5M elems
            long long e = ((long long)base + j * 256) * 4;
            if (v.x) { long long ek = e;     g_idx[(int)(ek % NMOVES)] = (int)(ek / NMOVES); }
            if (v.y) { long long ek = e + 1; g_idx[(int)(ek % NMOVES)] = (int)(ek / NMOVES); }
            if (v.z) { long long ek = e + 2; g_idx[(int)(ek % NMOVES)] = (int)(ek / NMOVES); }
            if (v.w) { long long ek = e + 3; g_idx[(int)(ek % NMOVES)] = (int)(ek / NMOVES); }
        }
    }
}

// ---------------------------------------------------------------------------
// Kernel B: out[b, m] = x[b, g_idx[m]].
// One CTA per batch row. Issue the x-row TMA copy BEFORE griddepcontrol.wait
// (x is independent of the build), then wait for build completion, read the
// indices, gather from smem, float2 .cs stores.
// ---------------------------------------------------------------------------
__global__ __launch_bounds__(256)
void policy_gather_kernel(const float* __restrict__ x,
                          float* __restrict__ out) {
    __shared__ __align__(128) float row[FLAT];           // 20 KB
    __shared__ __align__(8) unsigned long long mbar;

    const int tid = threadIdx.x;
    const int b = blockIdx.x;
    const uint32_t mbar_a = smem_u32(&mbar);
    const uint32_t row_a  = smem_u32(row);

    if (tid == 0) mbar_init(mbar_a, 1);
    __syncthreads();
    if (tid == 0) {
        mbar_expect_tx(mbar_a, ROW_BYTES);
        bulk_g2s(row_a, x + (size_t)b * FLAT, ROW_BYTES, mbar_a);
    }

    // Block until the build grid has fully completed (g_idx visible).
    pdl_wait();

    // Preload gather indices while the bulk copy is (possibly) in flight.
    const int2* idxp = reinterpret_cast<const int2*>(g_idx);
    const int2 i0 = idxp[tid];
    const int2 i1 = idxp[tid + 256];
    const int2 i2 = idxp[tid + 512];
    const bool has3 = tid < (NMOVES / 2 - 768);          // 161 threads
    int2 i3 = make_int2(0, 0);
    if (has3) i3 = idxp[tid + 768];

    mbar_wait(mbar_a, 0);

    float2* o = reinterpret_cast<float2*>(out + (size_t)b * NMOVES);
    float2 v;
    v.x = row[i0.x]; v.y = row[i0.y]; __stcs(o + tid,       v);
    v.x = row[i1.x]; v.y = row[i1.y]; __stcs(o + tid + 256, v);
    v.x = row[i2.x]; v.y = row[i2.y]; __stcs(o + tid + 512, v);
    if (has3) {
        v.x = row[i3.x]; v.y = row[i3.y]; __stcs(o + tid + 768, v);
    }
}

extern "C" void kernel_launch(void* const* d_in, const int* in_sizes, int n_in,
                              void* d_out, int out_size) {
    const float* x   = (const float*)d_in[0];   // [16384, 80, 8, 8] fp32
    const float* fc1 = (const float*)d_in[1];   // [5120, 1858] fp32
    float* out = (float*)d_out;                 // [16384, 1858] fp32

    // A: rebuild the selection index (38 MB scan, perfectly tiled).
    build_idx_kernel<<<1858, 256>>>(reinterpret_cast<const uint4*>(fc1));

    // B: the gather, launched with programmatic dependent launch so its
    // prologue (TMA staging of x rows) overlaps the tail of the build scan.
    cudaLaunchConfig_t cfg = {};
    cfg.gridDim  = dim3(BATCH);
    cfg.blockDim = dim3(256);
    cfg.dynamicSmemBytes = 0;
    cfg.stream = 0;
    cudaLaunchAttribute attr[1];
    attr[0].id = cudaLaunchAttributeProgrammaticStreamSerialization;
    attr[0].val.programmaticStreamSerializationAllowed = 1;
    cfg.attrs = attr;
    cfg.numAttrs = 1;
    cudaLaunchKernelEx(&cfg, policy_gather_kernel, x, out);
}